// round 7
// baseline (speedup 1.0000x reference)
#include <cuda_runtime.h>
#include <cstdint>

// Problem constants (fixed by the dataset)
#define HDIM   128          // memory dim
#define MSGDIM 256          // message dim
#define GDIM   384          // 3*HDIM
#define MAXB   200000       // number of updated nodes

// Scratch for gate pre-activations (allowed: __device__ globals, no cudaMalloc)
__device__ float g_gi[(size_t)MAXB * GDIM];   // X @ W_ih^T
__device__ float g_gh[(size_t)MAXB * GDIM];   // h @ W_hh^T

// ---------------------------------------------------------------------------
// Vectorized grid-stride copy (float4)
// ---------------------------------------------------------------------------
__global__ void copy_f4(const float4* __restrict__ src, float4* __restrict__ dst,
                        size_t n4) {
    size_t i = (size_t)blockIdx.x * blockDim.x + threadIdx.x;
    size_t stride = (size_t)gridDim.x * blockDim.x;
    for (; i < n4; i += stride) dst[i] = src[i];
}

// ---------------------------------------------------------------------------
// f32x2 packed-FMA helpers (FFMA2 — PTX-only form, 2x scalar FFMA throughput)
// ---------------------------------------------------------------------------
__device__ __forceinline__ unsigned long long fma2(unsigned long long a,
                                                   unsigned long long b,
                                                   unsigned long long c) {
    unsigned long long d;
    asm("fma.rn.f32x2 %0, %1, %2, %3;" : "=l"(d) : "l"(a), "l"(b), "l"(c));
    return d;
}
__device__ __forceinline__ unsigned long long pack2(float x) {
    unsigned long long d;
    asm("mov.b64 %0, {%1, %1};" : "=l"(d) : "f"(x));
    return d;
}
__device__ __forceinline__ void unpack2(unsigned long long v, float& lo, float& hi) {
    asm("mov.b64 {%0, %1}, %2;" : "=f"(lo), "=f"(hi) : "l"(v));
}

// ---------------------------------------------------------------------------
// Tiled SGEMM: C[b, j] = sum_k A[row(b), k] * W[j, k]
//   A : [*, K] row-major (optionally gathered through ids)
//   W : [GDIM, K] row-major
//   C : [B, GDIM] row-major (g_gi or g_gh, selected by `which`)
// Tile: BM=128 x BN=128 x BK=8, 256 threads, 8x8 outputs/thread, f32x2 FMAs.
// ---------------------------------------------------------------------------
template<int K>
__global__ void __launch_bounds__(256, 2)
gemm384(const float* __restrict__ A, const int* __restrict__ ids,
        const float* __restrict__ W, int which, int B) {
    __shared__ __align__(16) float As[8][128];
    __shared__ __align__(16) float Ws[8][128];

    float* __restrict__ C = which ? g_gh : g_gi;

    const int t  = threadIdx.x;
    const int rb = blockIdx.x * 128;
    const int cb = blockIdx.y * 128;

    // ---- load mapping: 128 rows x 8 k per tile, 2 threads per row, float4 each
    const int lm = t >> 1;           // 0..127
    const int lk = (t & 1) * 4;      // 0 or 4

    int arow = rb + lm;
    if (arow >= B) arow = B - 1;                      // clamp (results discarded)
    const int  asrc = ids ? ids[arow] : arow;
    const float* Aptr = A + (size_t)asrc * K;
    const float* Wptr = W + (size_t)(cb + lm) * K;    // cb+lm <= 383, always valid

    // ---- compute mapping: 16x16 thread grid, 8 rows x 8 cols each
    const int tx = t & 15;           // col group
    const int ty = t >> 4;           // row group

    unsigned long long acc[8][4];
#pragma unroll
    for (int r = 0; r < 8; r++)
#pragma unroll
        for (int c = 0; c < 4; c++) acc[r][c] = 0ull;

    for (int k0 = 0; k0 < K; k0 += 8) {
        float4 av = *reinterpret_cast<const float4*>(Aptr + k0 + lk);
        float4 wv = *reinterpret_cast<const float4*>(Wptr + k0 + lk);
        __syncthreads();   // previous-iter smem reads complete
        As[lk + 0][lm] = av.x; As[lk + 1][lm] = av.y;
        As[lk + 2][lm] = av.z; As[lk + 3][lm] = av.w;
        Ws[lk + 0][lm] = wv.x; Ws[lk + 1][lm] = wv.y;
        Ws[lk + 2][lm] = wv.z; Ws[lk + 3][lm] = wv.w;
        __syncthreads();

#pragma unroll
        for (int k = 0; k < 8; k++) {
            float4 a0 = *reinterpret_cast<const float4*>(&As[k][ty * 8]);
            float4 a1 = *reinterpret_cast<const float4*>(&As[k][ty * 8 + 4]);
            const unsigned long long* bp =
                reinterpret_cast<const unsigned long long*>(&Ws[k][tx * 8]);
            unsigned long long b0 = bp[0], b1 = bp[1], b2 = bp[2], b3 = bp[3];
            unsigned long long ap[8] = {
                pack2(a0.x), pack2(a0.y), pack2(a0.z), pack2(a0.w),
                pack2(a1.x), pack2(a1.y), pack2(a1.z), pack2(a1.w)};
#pragma unroll
            for (int r = 0; r < 8; r++) {
                acc[r][0] = fma2(ap[r], b0, acc[r][0]);
                acc[r][1] = fma2(ap[r], b1, acc[r][1]);
                acc[r][2] = fma2(ap[r], b2, acc[r][2]);
                acc[r][3] = fma2(ap[r], b3, acc[r][3]);
            }
        }
    }

    // ---- store 8x8 per thread (two float4 per row)
#pragma unroll
    for (int r = 0; r < 8; r++) {
        int row = rb + ty * 8 + r;
        if (row < B) {
            float* Cp = C + (size_t)row * GDIM + cb + tx * 8;
            float o0, o1, o2, o3, o4, o5, o6, o7;
            unpack2(acc[r][0], o0, o1);
            unpack2(acc[r][1], o2, o3);
            unpack2(acc[r][2], o4, o5);
            unpack2(acc[r][3], o6, o7);
            *reinterpret_cast<float4*>(Cp)     = make_float4(o0, o1, o2, o3);
            *reinterpret_cast<float4*>(Cp + 4) = make_float4(o4, o5, o6, o7);
        }
    }
}

// ---------------------------------------------------------------------------
// GRU epilogue + scatter. One block per updated node, 128 threads (one per h).
//   r = sig(i_r + h_r); z = sig(i_z + h_z); n = tanh(i_n + r*h_n)
//   h_new = (1-z)*n + z*h
// ---------------------------------------------------------------------------
__global__ void gru_epilogue(const float* __restrict__ memory,
                             const int* __restrict__ ids,
                             const float* __restrict__ ts,
                             const float* __restrict__ b_ih,
                             const float* __restrict__ b_hh,
                             float* __restrict__ out_mem,
                             float* __restrict__ out_lu,
                             int B) {
    int b = blockIdx.x;
    if (b >= B) return;
    int h = threadIdx.x;                 // 0..127
    int node = ids[b];

    const float* gi = g_gi + (size_t)b * GDIM;
    const float* gh = g_gh + (size_t)b * GDIM;

    float i_r = gi[h]       + b_ih[h];
    float i_z = gi[128 + h] + b_ih[128 + h];
    float i_n = gi[256 + h] + b_ih[256 + h];
    float h_r = gh[h]       + b_hh[h];
    float h_z = gh[128 + h] + b_hh[128 + h];
    float h_n = gh[256 + h] + b_hh[256 + h];

    float hprev = memory[(size_t)node * HDIM + h];

    float r = 1.0f / (1.0f + expf(-(i_r + h_r)));
    float z = 1.0f / (1.0f + expf(-(i_z + h_z)));
    float n = tanhf(i_n + r * h_n);
    float hnew = (1.0f - z) * n + z * hprev;

    out_mem[(size_t)node * HDIM + h] = hnew;
    if (h == 0) out_lu[node] = ts[b];
}

// ---------------------------------------------------------------------------
// kernel_launch
// Inputs (metadata order):
//   0 memory [N_NODES*128] f32      1 last_update [N_NODES] f32
//   2 unique_node_ids [B] i32       3 unique_messages [B*256] f32
//   4 timestamps [B] f32            5 W_ih [384*256] f32
//   6 W_hh [384*128] f32            7 b_ih [384] f32   8 b_hh [384] f32
// Output: [N_NODES*128 updated_memory | N_NODES updated_last_update] f32
// ---------------------------------------------------------------------------
extern "C" void kernel_launch(void* const* d_in, const int* in_sizes, int n_in,
                              void* d_out, int out_size) {
    const float* memory      = (const float*)d_in[0];
    const float* last_update = (const float*)d_in[1];
    const int*   ids         = (const int*)d_in[2];
    const float* messages    = (const float*)d_in[3];
    const float* ts          = (const float*)d_in[4];
    const float* W_ih        = (const float*)d_in[5];
    const float* W_hh        = (const float*)d_in[6];
    const float* b_ih        = (const float*)d_in[7];
    const float* b_hh        = (const float*)d_in[8];

    const int    B      = in_sizes[2];
    const size_t memN   = (size_t)in_sizes[0];   // N_NODES * 128
    const size_t nNodes = (size_t)in_sizes[1];   // N_NODES

    float* out_mem = (float*)d_out;
    float* out_lu  = (float*)d_out + memN;

    // Phase 0: pass-through copies (overwritten rows fixed up by the epilogue)
    copy_f4<<<2960, 256>>>((const float4*)memory, (float4*)out_mem, memN / 4);
    copy_f4<<<256, 256>>>((const float4*)last_update, (float4*)out_lu, nNodes / 4);

    // Phase 1: gate pre-activations
    dim3 ggrid((B + 127) / 128, GDIM / 128);
    gemm384<MSGDIM><<<ggrid, 256>>>(messages, nullptr, W_ih, /*which=*/0, B);
    gemm384<HDIM>  <<<ggrid, 256>>>(memory,   ids,     W_hh, /*which=*/1, B);

    // Phase 2: GRU cell + scatter
    gru_epilogue<<<B, HDIM>>>(memory, ids, ts, b_ih, b_hh, out_mem, out_lu, B);
}

// round 10
// speedup vs baseline: 1.3120x; 1.3120x over previous
#include <cuda_runtime.h>
#include <mma.h>
#include <cstdint>

using namespace nvcuda;

// ---------------------------------------------------------------------------
// Problem constants
// ---------------------------------------------------------------------------
#define HDIM    128
#define MSGDIM  256
#define GDIM    384
#define MAXROWS 200192      // 200000 rounded up to a multiple of 128 (pad rows)

// Gate pre-activation scratch (device globals: no cudaMalloc allowed)
__device__ float g_gi[(size_t)MAXROWS * GDIM];   // X @ W_ih^T
__device__ float g_gh[(size_t)MAXROWS * GDIM];   // h @ W_hh^T

// ---------------------------------------------------------------------------
// Pass-through copy (float4 grid-stride)
// ---------------------------------------------------------------------------
__global__ void copy_f4(const float4* __restrict__ src, float4* __restrict__ dst,
                        size_t n4) {
    size_t i = (size_t)blockIdx.x * blockDim.x + threadIdx.x;
    size_t stride = (size_t)gridDim.x * blockDim.x;
    for (; i < n4; i += stride) dst[i] = src[i];
}

// ---------------------------------------------------------------------------
// wmma tf32 GEMM:  C[b, j] = sum_k A[row(b), k] * W[j, k]
//   A : [*, K] row-major (optionally gathered through ids)
//   W : [GDIM, K] row-major  (== matrix_b col_major with ldb = K)
//   C : [MAXROWS, GDIM] scratch (g_gi / g_gh via `which`)
// CTA tile 128x128xBK32, 256 threads (8 warps in a 2x4 grid, warp tile 64x32),
// cp.async double-buffered smem.
// ---------------------------------------------------------------------------
#define LDA 36                                // 32 + 4 pad (multiple of 4)
static constexpr int SMEM_FLOATS = 2 * 2 * 128 * LDA;   // A+W, 2 stages
static constexpr int SMEM_BYTES  = SMEM_FLOATS * 4;     // 73728

template<int K>
__global__ void __launch_bounds__(256, 2)
gemm_wmma(const float* __restrict__ A, const int* __restrict__ ids,
          const float* __restrict__ W, int which, int B) {
    extern __shared__ float sm[];
    float* As = sm;                     // [2][128][LDA]
    float* Ws = sm + 2 * 128 * LDA;     // [2][128][LDA]
    float* __restrict__ C = which ? g_gh : g_gi;

    const int t  = threadIdx.x;
    const int rb = blockIdx.x * 128;
    const int cb = blockIdx.y * 128;

    // ---- global->smem mapping: 2 threads per row, 16 floats (4 float4) each
    const int lm = t >> 1;
    const int lk = (t & 1) * 16;

    int arow = rb + lm; if (arow > B - 1) arow = B - 1;   // clamp (pad rows)
    const int asrc = ids ? ids[arow] : arow;
    const float* Ap = A + (size_t)asrc * K + lk;
    const float* Wp = W + (size_t)(cb + lm) * K + lk;     // cb+lm <= 383

    const uint32_t sA = (uint32_t)__cvta_generic_to_shared(As + lm * LDA + lk);
    const uint32_t sW = (uint32_t)__cvta_generic_to_shared(Ws + lm * LDA + lk);
    const uint32_t bufB = 128 * LDA * 4;   // bytes per stage buffer

    // ---- warp tiling: 2x4 warps, each 64 rows x 32 cols
    const int wid = t >> 5;
    const int wm  = wid >> 2;   // 0..1
    const int wn  = wid & 3;    // 0..3

    wmma::fragment<wmma::accumulator, 16, 16, 8, float> acc[4][2];
    #pragma unroll
    for (int mf = 0; mf < 4; mf++)
        #pragma unroll
        for (int nf = 0; nf < 2; nf++)
            wmma::fill_fragment(acc[mf][nf], 0.0f);

    constexpr int S = K / 32;

    auto load_stage = [&](int s) {
        const uint32_t boff = (uint32_t)(s & 1) * bufB;
        const float* ap = Ap + s * 32;
        const float* wp = Wp + s * 32;
        #pragma unroll
        for (int q = 0; q < 4; q++) {
            asm volatile("cp.async.cg.shared.global [%0], [%1], 16;"
                         :: "r"(sA + boff + q * 16), "l"(ap + q * 4));
            asm volatile("cp.async.cg.shared.global [%0], [%1], 16;"
                         :: "r"(sW + boff + q * 16), "l"(wp + q * 4));
        }
        asm volatile("cp.async.commit_group;");
    };

    load_stage(0);

    for (int s = 0; s < S; s++) {
        if (s + 1 < S) {
            load_stage(s + 1);
            asm volatile("cp.async.wait_group 1;");
        } else {
            asm volatile("cp.async.wait_group 0;");
        }
        __syncthreads();

        const float* Ab = As + (s & 1) * 128 * LDA;
        const float* Wb = Ws + (s & 1) * 128 * LDA;

        #pragma unroll
        for (int ks = 0; ks < 4; ks++) {
            wmma::fragment<wmma::matrix_a, 16, 16, 8,
                           wmma::precision::tf32, wmma::row_major> af[4];
            wmma::fragment<wmma::matrix_b, 16, 16, 8,
                           wmma::precision::tf32, wmma::col_major> bf[2];
            #pragma unroll
            for (int mf = 0; mf < 4; mf++) {
                wmma::load_matrix_sync(af[mf], Ab + (wm * 64 + mf * 16) * LDA + ks * 8, LDA);
                #pragma unroll
                for (int e = 0; e < af[mf].num_elements; e++)
                    af[mf].x[e] = wmma::__float_to_tf32(af[mf].x[e]);
            }
            #pragma unroll
            for (int nf = 0; nf < 2; nf++) {
                wmma::load_matrix_sync(bf[nf], Wb + (wn * 32 + nf * 16) * LDA + ks * 8, LDA);
                #pragma unroll
                for (int e = 0; e < bf[nf].num_elements; e++)
                    bf[nf].x[e] = wmma::__float_to_tf32(bf[nf].x[e]);
            }
            #pragma unroll
            for (int mf = 0; mf < 4; mf++)
                #pragma unroll
                for (int nf = 0; nf < 2; nf++)
                    wmma::mma_sync(acc[mf][nf], af[mf], bf[nf], acc[mf][nf]);
        }
        __syncthreads();
    }

    // ---- store (pad rows land in scratch rows [B, MAXROWS), never read)
    #pragma unroll
    for (int mf = 0; mf < 4; mf++) {
        const int row = rb + wm * 64 + mf * 16;
        #pragma unroll
        for (int nf = 0; nf < 2; nf++) {
            const int col = cb + wn * 32 + nf * 16;
            wmma::store_matrix_sync(C + (size_t)row * GDIM + col,
                                    acc[mf][nf], GDIM, wmma::mem_row_major);
        }
    }
}

// ---------------------------------------------------------------------------
// GRU epilogue + scatter. One block per updated node, 128 threads (one per h).
// ---------------------------------------------------------------------------
__global__ void gru_epilogue(const float* __restrict__ memory,
                             const int* __restrict__ ids,
                             const float* __restrict__ ts,
                             const float* __restrict__ b_ih,
                             const float* __restrict__ b_hh,
                             float* __restrict__ out_mem,
                             float* __restrict__ out_lu,
                             int B) {
    int b = blockIdx.x;
    if (b >= B) return;
    int h = threadIdx.x;                 // 0..127
    int node = ids[b];

    const float* gi = g_gi + (size_t)b * GDIM;
    const float* gh = g_gh + (size_t)b * GDIM;

    float i_r = gi[h]       + b_ih[h];
    float i_z = gi[128 + h] + b_ih[128 + h];
    float i_n = gi[256 + h] + b_ih[256 + h];
    float h_r = gh[h]       + b_hh[h];
    float h_z = gh[128 + h] + b_hh[128 + h];
    float h_n = gh[256 + h] + b_hh[256 + h];

    float hprev = memory[(size_t)node * HDIM + h];

    float r = 1.0f / (1.0f + expf(-(i_r + h_r)));
    float z = 1.0f / (1.0f + expf(-(i_z + h_z)));
    float n = tanhf(i_n + r * h_n);
    float hnew = (1.0f - z) * n + z * hprev;

    out_mem[(size_t)node * HDIM + h] = hnew;
    if (h == 0) out_lu[node] = ts[b];
}

// ---------------------------------------------------------------------------
// kernel_launch
// Inputs: 0 memory 1 last_update 2 ids 3 messages 4 ts 5 W_ih 6 W_hh 7 b_ih 8 b_hh
// Output: [memory' | last_update'] f32
// ---------------------------------------------------------------------------
extern "C" void kernel_launch(void* const* d_in, const int* in_sizes, int n_in,
                              void* d_out, int out_size) {
    const float* memory      = (const float*)d_in[0];
    const float* last_update = (const float*)d_in[1];
    const int*   ids         = (const int*)d_in[2];
    const float* messages    = (const float*)d_in[3];
    const float* ts          = (const float*)d_in[4];
    const float* W_ih        = (const float*)d_in[5];
    const float* W_hh        = (const float*)d_in[6];
    const float* b_ih        = (const float*)d_in[7];
    const float* b_hh        = (const float*)d_in[8];

    const int    B      = in_sizes[2];
    const size_t memN   = (size_t)in_sizes[0];
    const size_t nNodes = (size_t)in_sizes[1];

    float* out_mem = (float*)d_out;
    float* out_lu  = (float*)d_out + memN;

    cudaFuncSetAttribute(gemm_wmma<MSGDIM>,
                         cudaFuncAttributeMaxDynamicSharedMemorySize, SMEM_BYTES);
    cudaFuncSetAttribute(gemm_wmma<HDIM>,
                         cudaFuncAttributeMaxDynamicSharedMemorySize, SMEM_BYTES);

    // Phase 0: pass-through copies (updated rows overwritten in phase 2)
    copy_f4<<<2960, 256>>>((const float4*)memory, (float4*)out_mem, memN / 4);
    copy_f4<<<256, 256>>>((const float4*)last_update, (float4*)out_lu, nNodes / 4);

    // Phase 1: gate pre-activations on the tensor pipe (wmma tf32)
    dim3 ggrid((B + 127) / 128, GDIM / 128);
    gemm_wmma<MSGDIM><<<ggrid, 256, SMEM_BYTES>>>(messages, nullptr, W_ih, 0, B);
    gemm_wmma<HDIM>  <<<ggrid, 256, SMEM_BYTES>>>(memory,   ids,     W_hh, 1, B);

    // Phase 2: GRU cell + scatter
    gru_epilogue<<<B, HDIM>>>(memory, ids, ts, b_ih, b_hh, out_mem, out_lu, B);
}